// round 3
// baseline (speedup 1.0000x reference)
#include <cuda_runtime.h>

// Problem constants (fixed by the reference)
#define BB     32
#define TXX    4096
#define DD     512
#define SPLITS 16
#define TCHUNK (TXX / SPLITS)   // 256

// Per-batch 1/sum(mask) scratch (no cudaMalloc allowed)
__device__ float g_inv[BB];

// Kernel 0: per-batch mask count -> g_inv, and zero the context region of out.
__global__ void prep_kernel(const int* __restrict__ mask,
                            const int* __restrict__ um_p,
                            float* __restrict__ out) {
    const int b   = blockIdx.x;     // 32 blocks
    const int tid = threadIdx.x;    // 256 threads
    const bool um = (um_p[0] != 0); // works for int32 1 and float32 1.0f bits

    int cnt = 0;
    for (int t = tid; t < TXX; t += 256)
        cnt += (mask[b * TXX + t] != 0);

    __shared__ int sdata[256];
    sdata[tid] = cnt;
    __syncthreads();
#pragma unroll
    for (int s = 128; s > 0; s >>= 1) {
        if (tid < s) sdata[tid] += sdata[tid + s];
        __syncthreads();
    }
    if (tid == 0) {
        int c = sdata[0] > 0 ? sdata[0] : 1;
        g_inv[b] = um ? (1.0f / (float)c) : 1.0f;
    }

    // Zero context region out[0 .. B*D) (d_out is poisoned 0xAA)
    for (int i = b * 256 + tid; i < BB * DD; i += 32 * 256)
        out[i] = 0.0f;
}

// Kernel 1: write alpha, accumulate masked row-sum of a into context via atomics.
// Grid: (SPLITS, BB), 128 threads; each thread owns 4 consecutive d via float4.
__global__ void ctx_alpha_kernel(const float* __restrict__ a,
                                 const int* __restrict__ mask,
                                 const int* __restrict__ um_p,
                                 float* __restrict__ out) {
    const int s   = blockIdx.x;
    const int b   = blockIdx.y;
    const int tid = threadIdx.x;     // 128
    const bool um = (um_p[0] != 0);
    const float inv = g_inv[b];
    const int t0 = s * TCHUNK;

    __shared__ int smask[TCHUNK];

    // alpha[b, t] = um ? (mask ? 1/s : 0) : 1; also stage mask into SMEM.
    float* alpha = out + BB * DD + (size_t)b * TXX;
#pragma unroll
    for (int t = tid; t < TCHUNK; t += 128) {
        int m = (mask[b * TXX + t0 + t] != 0);
        smask[t] = m;
        alpha[t0 + t] = um ? (m ? inv : 0.0f) : 1.0f;
    }
    __syncthreads();

    // Masked accumulation over this block's t-chunk.
    // Predicate is uniform across the block per t -> predicated-off LDG.128
    // skips the DRAM transaction entirely (~halves traffic for 50% mask).
    float4 acc = make_float4(0.f, 0.f, 0.f, 0.f);
    const float4* arow = (const float4*)(a + ((size_t)b * TXX + t0) * DD) + tid;
#pragma unroll 8
    for (int t = 0; t < TCHUNK; t++) {
        bool keep = (!um) || (smask[t] != 0);
        if (keep) {
            float4 v = arow[(size_t)t * (DD / 4)];
            acc.x += v.x; acc.y += v.y; acc.z += v.z; acc.w += v.w;
        }
    }

    // context[b, d] += inv * partial  (spread-address REDG, cheap)
    float* ctx = out + (size_t)b * DD + tid * 4;
    atomicAdd(ctx + 0, acc.x * inv);
    atomicAdd(ctx + 1, acc.y * inv);
    atomicAdd(ctx + 2, acc.z * inv);
    atomicAdd(ctx + 3, acc.w * inv);
}

extern "C" void kernel_launch(void* const* d_in, const int* in_sizes, int n_in,
                              void* d_out, int out_size) {
    // metadata order: a, h, coverage, X_mask, Wa, Wh, Wc, V, use_coverage, use_masking
    const float* a    = (const float*)d_in[0];
    const int*   mask = (const int*)  d_in[3];
    const int*   um   = (const int*)  d_in[9];
    float* out = (float*)d_out;

    prep_kernel<<<BB, 256>>>(mask, um, out);
    dim3 grid(SPLITS, BB);
    ctx_alpha_kernel<<<grid, 128>>>(a, mask, um, out);
}

// round 5
// speedup vs baseline: 2.1265x; 2.1265x over previous
#include <cuda_runtime.h>

// Problem constants (fixed by the reference)
#define BB     32
#define TXX    4096
#define DD     512
#define SPLITS 32
#define TCHUNK (TXX / SPLITS)   // 128
#define NT     256              // threads per ctx block (2 rows of D per iter)

// Per-batch 1/sum(mask) scratch (no cudaMalloc allowed)
__device__ float g_inv[BB];

// Kernel 0: per-batch mask count -> g_inv, and zero the context region of out.
__global__ void prep_kernel(const int* __restrict__ mask,
                            const int* __restrict__ um_p,
                            float* __restrict__ out) {
    const int b   = blockIdx.x;     // 32 blocks
    const int tid = threadIdx.x;    // 256 threads
    const bool um = (um_p[0] != 0);

    // Vectorized mask count: 4096 ints = 1024 int4 per batch
    const int4* m4 = (const int4*)(mask + b * TXX);
    int cnt = 0;
#pragma unroll
    for (int i = tid; i < TXX / 4; i += 256) {
        int4 v = m4[i];
        cnt += (v.x != 0) + (v.y != 0) + (v.z != 0) + (v.w != 0);
    }

    __shared__ int sdata[256];
    sdata[tid] = cnt;
    __syncthreads();
#pragma unroll
    for (int s = 128; s > 0; s >>= 1) {
        if (tid < s) sdata[tid] += sdata[tid + s];
        __syncthreads();
    }
    if (tid == 0) {
        int c = sdata[0] > 0 ? sdata[0] : 1;
        g_inv[b] = um ? (1.0f / (float)c) : 1.0f;
    }

    // Zero context region out[0 .. B*D) (d_out is poisoned 0xAA)
    for (int i = b * 256 + tid; i < BB * DD; i += 32 * 256)
        out[i] = 0.0f;
}

// Kernel 1: write alpha, compact kept rows, masked row-sum with unconditional
// batched LDG.128, SMEM half-reduction, then global atomics.
// Grid: (SPLITS, BB), NT=256 threads; thread -> (half = tid>>7, col = tid&127).
__global__ void __launch_bounds__(NT)
ctx_alpha_kernel(const float* __restrict__ a,
                 const int* __restrict__ mask,
                 const int* __restrict__ um_p,
                 float* __restrict__ out) {
    const int s   = blockIdx.x;
    const int b   = blockIdx.y;
    const int tid = threadIdx.x;
    const bool um = (um_p[0] != 0);
    const float inv = g_inv[b];
    const int t0 = s * TCHUNK;

    __shared__ int   slist[TCHUNK];
    __shared__ int   scnt;
    __shared__ float4 sctx[DD / 4];   // 128 float4

    if (tid == 0) scnt = 0;
    __syncthreads();

    // Stage: one thread per t in this chunk. Write alpha; compact kept indices.
    float* alpha = out + BB * DD + (size_t)b * TXX;
    if (tid < TCHUNK) {
        int t = t0 + tid;
        int m = (mask[b * TXX + t] != 0);
        int keep = um ? m : 1;
        alpha[t] = um ? (m ? inv : 0.0f) : 1.0f;
        if (keep) {
            int p = atomicAdd(&scnt, 1);
            slist[p] = tid;
        }
    }
    __syncthreads();

    const int n    = scnt;
    const int col  = tid & 127;
    const int half = tid >> 7;

    // Unconditional loads over the compacted list -> front-batched LDG.128.
    const float4* abase = (const float4*)(a + ((size_t)b * TXX + t0) * DD);
    float4 acc = make_float4(0.f, 0.f, 0.f, 0.f);
#pragma unroll 4
    for (int i = half; i < n; i += 2) {
        int t = slist[i];                       // LDS broadcast within warp
        float4 v = abase[(size_t)t * (DD / 4) + col];
        acc.x += v.x; acc.y += v.y; acc.z += v.z; acc.w += v.w;
    }

    // Reduce the two halves through SMEM, then half 1 issues the atomics.
    if (half == 0) sctx[col] = acc;
    __syncthreads();
    if (half == 1) {
        float4 o = sctx[col];
        acc.x += o.x; acc.y += o.y; acc.z += o.z; acc.w += o.w;
        float* ctx = out + (size_t)b * DD + col * 4;
        atomicAdd(ctx + 0, acc.x * inv);
        atomicAdd(ctx + 1, acc.y * inv);
        atomicAdd(ctx + 2, acc.z * inv);
        atomicAdd(ctx + 3, acc.w * inv);
    }
}

extern "C" void kernel_launch(void* const* d_in, const int* in_sizes, int n_in,
                              void* d_out, int out_size) {
    // metadata order: a, h, coverage, X_mask, Wa, Wh, Wc, V, use_coverage, use_masking
    const float* a    = (const float*)d_in[0];
    const int*   mask = (const int*)  d_in[3];
    const int*   um   = (const int*)  d_in[9];
    float* out = (float*)d_out;

    prep_kernel<<<BB, 256>>>(mask, um, out);
    dim3 grid(SPLITS, BB);
    ctx_alpha_kernel<<<grid, NT>>>(a, mask, um, out);
}